// round 9
// baseline (speedup 1.0000x reference)
#include <cuda_runtime.h>
#include <cstdint>

// PatchEmbed permute: x[16,64,256,256] f32 -> out[16, 64*64, 64*4*4]
// out[n, wp, hp, c, pi, pj] = x[n, c, hp*4+pi, wp*4+pj]
// pj (4 floats) => float4 units. Per (n, hp): transpose M[cp=256][wp=64]
// of float4 where cp = c*4+pi.
//   input  f4 idx = ((n*64 + c)*256 + hp*4 + pi)*64 + wp   (contiguous in wp)
//   output f4 idx = ((n*64 + wp)*64 + hp)*256 + cp          (contiguous in cp)
//
// R9: warp-autonomous tiles -- NO block barriers. Each warp owns a private
// 4(cp) x 32(wp) f4 tile (2KB smem slice); __syncwarp replaces __syncthreads
// so warps free-run with zero cross-warp arrival skew. Loads: 512B/warp
// coalesced. Stores: 8 rows x 64B sector-aligned chunks (100% sector eff).
// Swizzle col = wpl ^ (cpl<<1) is conflict-free in both smem phases.
// 256 thr, 16KB/block, __launch_bounds__(256,8) -> 64 warps/SM.

#define N_ 16
#define C_ 64
#define HP_ 64
#define WP_ 64
#define CP_ 256            // C_*4
#define THREADS 256
#define NWARP (THREADS / 32)
#define NDATA    (N_ * C_ * 256 * 256)     // data size in floats

__global__ __launch_bounds__(THREADS, 8)
void patch_permute_kernel(const float4* __restrict__ in, float4* __restrict__ out,
                          int tail_count) {
    __shared__ float4 tile[NWARP][4][32];   // 2KB per warp, XOR-swizzled

    const int cpt  = blockIdx.x;   // 0..7   (cp in [cpt*32, cpt*32+32))
    const int hp   = blockIdx.y;   // 0..63
    const int n    = blockIdx.z;   // 0..15
    const int tid  = threadIdx.x;
    const int w    = tid >> 5;     // warp 0..7
    const int lane = tid & 31;

    // ---- fused tail write (ori_shape = 16,64,256,256), one block only ----
    if (cpt == 0 && hp == 0 && n == 0 && tid < 4 && tid < tail_count) {
        const float vals[4] = {16.0f, 64.0f, 256.0f, 256.0f};
        ((float*)out)[NDATA + tid] = vals[tid];
    }

    const int cpbase = cpt * 32 + w * 4;   // this warp's 4 cp rows

#pragma unroll
    for (int wpc = 0; wpc < 2; wpc++) {    // wp chunks of 32
        // ---- load: 4 coalesced 512B warp reads ----
#pragma unroll
        for (int cpl = 0; cpl < 4; cpl++) {
            int cp = cpbase + cpl;
            int c  = cp >> 2;
            int pi = cp & 3;
            int wp = wpc * 32 + lane;
            int in_idx = ((n * C_ + c) * 256 + hp * 4 + pi) * WP_ + wp;
            tile[w][cpl][lane ^ (cpl << 1)] = in[in_idx];
        }
        __syncwarp();

        // ---- store: 8 rows x 64B sector-aligned chunks per warp op ----
#pragma unroll
        for (int i = 0; i < 4; i++) {
            int idx = i * 32 + lane;
            int wpl = idx >> 2;            // 0..31
            int cpl = idx & 3;             // 0..3
            int wp  = wpc * 32 + wpl;
            int cp  = cpbase + cpl;
            int out_idx = ((n * WP_ + wp) * HP_ + hp) * CP_ + cp;
            out[out_idx] = tile[w][cpl][wpl ^ (cpl << 1)];
        }
        __syncwarp();   // buffer reuse fence for next wp chunk
    }
}

extern "C" void kernel_launch(void* const* d_in, const int* in_sizes, int n_in,
                              void* d_out, int out_size) {
    (void)in_sizes; (void)n_in;
    const float4* in  = (const float4*)d_in[0];
    float4*       out = (float4*)d_out;

    int tail_count = out_size > NDATA ? (out_size - NDATA) : 0;

    dim3 grid(CP_ / 32, HP_, N_);   // 8 x 64 x 16 = 8192 blocks
    patch_permute_kernel<<<grid, THREADS>>>(in, out, tail_count);
}